// round 12
// baseline (speedup 1.0000x reference)
#include <cuda_runtime.h>
#include <math.h>
#include <stdint.h>

#define GRID 128
#define NTHR 512
#define Bv   128
#define Sv   256
#define HDv  512
#define APAD 134          // L1 As row pad
#define A2PADK 17         // L2 As k-major row: 16 rows + 1 pad
#define A2MAT  2192       // L2 As per-mat stride (2176+16 -> bank shift 16)
#define SM_FLOATS 8480    // max(L1: 32*134+128*32=8384, L2: 2*2192+2*2048=8480)

// Persistent device scratch (allocation-free).
__device__ float    g_X[Bv * Sv];        // current SDE state
__device__ float    g_H[2 * Bv * HDv];   // tanh hidden: [0]=drift, [1]=sigma
__device__ unsigned g_bar;               // grid barrier counter (monotone)

__global__ void k_zero() { g_bar = 0u; }

// Grid barrier: release-add + acquire-poll (128 CTAs, all co-resident).
__device__ __forceinline__ void grid_bar(unsigned goal) {
    __syncthreads();
    if (threadIdx.x == 0) {
        unsigned long long ga;
        asm volatile("cvta.to.global.u64 %0, %1;" : "=l"(ga) : "l"(&g_bar));
        asm volatile("red.release.gpu.global.add.u32 [%0], 1;" :: "l"(ga) : "memory");
        unsigned v;
        do {
            asm volatile("ld.acquire.gpu.global.u32 %0, [%1];" : "=r"(v) : "l"(ga) : "memory");
        } while (v < goal);
    }
    __syncthreads();
}

// ---------------------------------------------------------------------------
// L1: 32x32 tile of H = tanh(X @ W1 + b1). K=256 in 2 pipelined passes of 128.
// 8 K-groups x 64 thr, 4x4 micro-tile, smem reduction. (R10 layout + prefetch)
// ---------------------------------------------------------------------------
__device__ __forceinline__ void gemm_l1(
    const float* __restrict__ A,            // g_X [128][256]
    const float* __restrict__ W,            // W1  [256][512]
    const float* __restrict__ bias,
    float* __restrict__ Out,                // H   [128][512]
    int m0, int n0, float* sm)
{
    float* As = sm;               // [32][APAD]
    float* Bs = sm + 32 * APAD;   // [128][32]
    const int t  = threadIdx.x;
    const int g  = t >> 6;
    const int tt = t & 63;
    const int tm = tt >> 3;
    const int tn = tt & 7;

    float acc[4][4];
#pragma unroll
    for (int i = 0; i < 4; i++)
#pragma unroll
        for (int j = 0; j < 4; j++) acc[i][j] = 0.0f;

    float4 pa[2], pb[2];
#pragma unroll
    for (int it = 0; it < 2; it++) {          // prefetch pass 0
        int idx = it * 512 + t;
        int row = idx >> 5, c4 = (idx & 31) << 2;
        pa[it] = __ldcg((const float4*)(A + (m0 + row) * Sv + c4));
        int kr = idx >> 3, c4b = (idx & 7) << 2;
        pb[it] = __ldg((const float4*)(W + kr * HDv + n0 + c4b));
    }

#pragma unroll
    for (int p = 0; p < 2; p++) {
#pragma unroll
        for (int it = 0; it < 2; it++) {      // stage regs -> smem
            int idx = it * 512 + t;
            int row = idx >> 5, c4 = (idx & 31) << 2;
            *((float2*)(As + row * APAD + c4))     = make_float2(pa[it].x, pa[it].y);
            *((float2*)(As + row * APAD + c4 + 2)) = make_float2(pa[it].z, pa[it].w);
            int kr = idx >> 3, c4b = (idx & 7) << 2;
            *((float4*)(Bs + kr * 32 + c4b)) = pb[it];
        }
        __syncthreads();
        if (p == 0) {                         // prefetch pass 1
#pragma unroll
            for (int it = 0; it < 2; it++) {
                int idx = it * 512 + t;
                int row = idx >> 5, c4 = (idx & 31) << 2;
                pa[it] = __ldcg((const float4*)(A + (m0 + row) * Sv + 128 + c4));
                int kr = idx >> 3, c4b = (idx & 7) << 2;
                pb[it] = __ldg((const float4*)(W + (128 + kr) * HDv + n0 + c4b));
            }
        }
        const int k0 = g * 16;
#pragma unroll
        for (int kk = 0; kk < 16; kk++) {
            const int k = k0 + kk;
            float a0 = As[(tm * 4 + 0) * APAD + k];
            float a1 = As[(tm * 4 + 1) * APAD + k];
            float a2 = As[(tm * 4 + 2) * APAD + k];
            float a3 = As[(tm * 4 + 3) * APAD + k];
            float4 b = *((const float4*)(Bs + k * 32 + tn * 4));
            acc[0][0] = fmaf(a0, b.x, acc[0][0]); acc[0][1] = fmaf(a0, b.y, acc[0][1]);
            acc[0][2] = fmaf(a0, b.z, acc[0][2]); acc[0][3] = fmaf(a0, b.w, acc[0][3]);
            acc[1][0] = fmaf(a1, b.x, acc[1][0]); acc[1][1] = fmaf(a1, b.y, acc[1][1]);
            acc[1][2] = fmaf(a1, b.z, acc[1][2]); acc[1][3] = fmaf(a1, b.w, acc[1][3]);
            acc[2][0] = fmaf(a2, b.x, acc[2][0]); acc[2][1] = fmaf(a2, b.y, acc[2][1]);
            acc[2][2] = fmaf(a2, b.z, acc[2][2]); acc[2][3] = fmaf(a2, b.w, acc[2][3]);
            acc[3][0] = fmaf(a3, b.x, acc[3][0]); acc[3][1] = fmaf(a3, b.y, acc[3][1]);
            acc[3][2] = fmaf(a3, b.z, acc[3][2]); acc[3][3] = fmaf(a3, b.w, acc[3][3]);
        }
        __syncthreads();
    }

    // Reduce 8 K-groups via smem, tanh+bias, store H.
    float* R = sm;
#pragma unroll
    for (int i = 0; i < 4; i++) {
        *((float4*)(R + g * 1024 + (tm * 4 + i) * 32 + tn * 4)) =
            make_float4(acc[i][0], acc[i][1], acc[i][2], acc[i][3]);
    }
    __syncthreads();
#pragma unroll
    for (int h = 0; h < 2; h++) {
        int e = h * 512 + t;
        float s = R[e];
#pragma unroll
        for (int gg = 1; gg < 8; gg++) s += R[gg * 1024 + e];
        int m = e >> 5, n = e & 31;
        s = tanhf(s + __ldg(bias + n0 + n));
        __stcg(Out + (m0 + m) * HDv + n0 + n, s);
    }
}

// ---------------------------------------------------------------------------
// L2 + update: 16x16 state tile. Both mats (drift, sigma) computed in this CTA
// over full K=512 (4 pipelined passes of 128), then x updated in-epilogue.
// Threads: mat = t>>8; per mat 8 warps = 8 K-groups; warp micro-tile 2x4
// covers the full 16x16 tile for its k-slice. Smem reduction over warps.
// ---------------------------------------------------------------------------
__device__ __forceinline__ void l2_update(
    const float* __restrict__ Wd2, const float* __restrict__ bd2,
    const float* __restrict__ Ws2, const float* __restrict__ bs2,
    const float* __restrict__ fgn_t,
    float* __restrict__ out, int N, int step,
    float dt, float nscale,
    int m0, int n0, float* sm)
{
    float* As = sm;                    // [2][128][A2PADK] k-major, per-mat stride A2MAT
    float* Bs = sm + 2 * A2MAT;        // [2][128][16]
    const int t    = threadIdx.x;
    const int mat  = t >> 8;
    const int tt   = t & 255;
    const int w    = tt >> 5;          // warp-in-mat 0..7
    const int lane = tt & 31;
    const int tm   = lane >> 2;        // 0..7 -> rows tm*2+{0,1}
    const int tn   = lane & 3;         // 0..3 -> cols tn*4+{0..3}

    // per-thread staging constants
    const int matA = (t & 31) >> 4;                       // A-stage mat
    const int rA   = t & 15;                              // A-stage row
    const float* Astage = g_H + matA * (Bv * HDv) + (m0 + rA) * HDv;
    const int krB  = t >> 2;                              // B-stage k row 0..127
    const int c4b  = (t & 3) << 2;

    // prefetch update operands (hidden behind 4 GEMM passes)
    float xold = 0.0f, fg = 0.0f;
    if (t < 256) {
        int gi_e = (m0 + (t >> 4)) * Sv + n0 + (t & 15);
        xold = __ldcg(&g_X[gi_e]);
        fg   = __ldcs(fgn_t + gi_e);
    }

    float acc[2][4];
#pragma unroll
    for (int i = 0; i < 2; i++)
#pragma unroll
        for (int j = 0; j < 4; j++) acc[i][j] = 0.0f;

    float4 pa[2], pb[2];
#pragma unroll
    for (int it = 0; it < 2; it++) {          // prefetch pass 0 (kp = 0)
        int c4 = (((it * 512 + t) >> 5) << 2);
        pa[it] = __ldcg((const float4*)(Astage + c4));
        const float* Wst = it ? Ws2 : Wd2;
        pb[it] = __ldg((const float4*)(Wst + krB * Sv + n0 + c4b));
    }

#pragma unroll
    for (int p = 0; p < 4; p++) {
#pragma unroll
        for (int it = 0; it < 2; it++) {      // stage regs -> smem
            int c4 = (((it * 512 + t) >> 5) << 2);
            float* a = As + matA * A2MAT + c4 * A2PADK + rA;
            a[0 * A2PADK] = pa[it].x;
            a[1 * A2PADK] = pa[it].y;
            a[2 * A2PADK] = pa[it].z;
            a[3 * A2PADK] = pa[it].w;
            *((float4*)(Bs + it * 2048 + krB * 16 + c4b)) = pb[it];
        }
        __syncthreads();
        if (p < 3) {                          // prefetch pass p+1
            const int kp = (p + 1) * 128;
#pragma unroll
            for (int it = 0; it < 2; it++) {
                int c4 = (((it * 512 + t) >> 5) << 2);
                pa[it] = __ldcg((const float4*)(Astage + kp + c4));
                const float* Wst = it ? Ws2 : Wd2;
                pb[it] = __ldg((const float4*)(Wst + (kp + krB) * Sv + n0 + c4b));
            }
        }
        const float* Asm = As + mat * A2MAT;
        const float* Bsm = Bs + mat * 2048;
#pragma unroll
        for (int kk = 0; kk < 16; kk++) {
            const int kl = w * 16 + kk;
            float a0 = Asm[kl * A2PADK + tm * 2];
            float a1 = Asm[kl * A2PADK + tm * 2 + 1];
            float4 b = *((const float4*)(Bsm + kl * 16 + tn * 4));
            acc[0][0] = fmaf(a0, b.x, acc[0][0]); acc[0][1] = fmaf(a0, b.y, acc[0][1]);
            acc[0][2] = fmaf(a0, b.z, acc[0][2]); acc[0][3] = fmaf(a0, b.w, acc[0][3]);
            acc[1][0] = fmaf(a1, b.x, acc[1][0]); acc[1][1] = fmaf(a1, b.y, acc[1][1]);
            acc[1][2] = fmaf(a1, b.z, acc[1][2]); acc[1][3] = fmaf(a1, b.w, acc[1][3]);
        }
        __syncthreads();
    }

    // Reduce 8 warps per mat via smem (overlays As region), then update x.
    float* R = sm;                            // [2][8][256]
#pragma unroll
    for (int i = 0; i < 2; i++) {
        *((float4*)(R + mat * 2048 + w * 256 + (tm * 2 + i) * 16 + tn * 4)) =
            make_float4(acc[i][0], acc[i][1], acc[i][2], acc[i][3]);
    }
    __syncthreads();
    if (t < 256) {
        float dsum = R[t], ssum = R[2048 + t];
#pragma unroll
        for (int gg = 1; gg < 8; gg++) {
            dsum += R[gg * 256 + t];
            ssum += R[2048 + gg * 256 + t];
        }
        const int col = t & 15;
        const int row = t >> 4;
        dsum += __ldg(bd2 + n0 + col);
        ssum += __ldg(bs2 + n0 + col);
        float x = xold + dsum * dt + ssum * (nscale * fg);
        const int gi_e = (m0 + row) * Sv + n0 + col;
        __stcg(&g_X[gi_e], x);
        __stcs(out + (size_t)(m0 + row) * (size_t)(N + 1) * Sv
                   + (size_t)(step + 1) * Sv + n0 + col, x);
    }
}

// ---------------------------------------------------------------------------
// One persistent kernel: init, then N x { L1 | bar | L2+update | bar }.
// ---------------------------------------------------------------------------
__global__ __launch_bounds__(NTHR) void k_fsde(
    const float* __restrict__ x0,
    const float* __restrict__ Wd1, const float* __restrict__ bd1,
    const float* __restrict__ Wd2, const float* __restrict__ bd2,
    const float* __restrict__ Ws1, const float* __restrict__ bs1,
    const float* __restrict__ Ws2, const float* __restrict__ bs2,
    const float* __restrict__ raw_h,
    const float* __restrict__ fgn,
    float* __restrict__ out, int N)
{
    __shared__ float sm[SM_FLOATS];

    const int bx = blockIdx.x;
    const int t  = threadIdx.x;

    // init: g_X and trajectory slice 0
    if (t < 256) {
        int gi = bx * 256 + t;
        float v = __ldg(x0 + gi);
        __stcg(&g_X[gi], v);
        out[(size_t)(gi >> 8) * (size_t)(N + 1) * Sv + (gi & (Sv - 1))] = v;
    }

    const float dt = 1.0f / (float)N;
    const float rh = __ldg(raw_h);
    const float Hh = 0.98f / (1.0f + expf(-rh)) + 0.01f;
    const float nscale = (float)exp((double)Hh * log(1.0 / (double)N)); // dt^H

    // L1 decode: 2 mats x 4 mtiles x 16 ntiles = 128 CTAs
    const int mat1 = bx >> 6;
    const int m01  = ((bx >> 4) & 3) * 32;
    const int n01  = (bx & 15) * 32;
    const float* W1 = mat1 ? Ws1 : Wd1;
    const float* b1 = mat1 ? bs1 : bd1;
    float* H1 = g_H + mat1 * (Bv * HDv);

    // L2 decode: 8 mtiles x 16 ntiles = 128 CTAs (16x16 state tiles)
    const int m02 = (bx >> 4) * 16;
    const int n02 = (bx & 15) * 16;

    unsigned goal = GRID;
    grid_bar(goal); goal += GRID;          // X published

    for (int step = 0; step < N; step++) {
        gemm_l1(g_X, W1, b1, H1, m01, n01, sm);
        grid_bar(goal); goal += GRID;      // H ready

        l2_update(Wd2, bd2, Ws2, bs2, fgn + (size_t)step * (Bv * Sv),
                  out, N, step, dt, nscale, m02, n02, sm);
        grid_bar(goal); goal += GRID;      // X ready for next step
    }
}

// ---------------------------------------------------------------------------
// Host launcher: 2 graph nodes, fully capturable, allocation-free.
// ---------------------------------------------------------------------------
extern "C" void kernel_launch(void* const* d_in, const int* in_sizes, int n_in,
                              void* d_out, int out_size) {
    const float* x0    = (const float*)d_in[0];
    const float* Wd1   = (const float*)d_in[1];
    const float* bd1   = (const float*)d_in[2];
    const float* Wd2   = (const float*)d_in[3];
    const float* bd2   = (const float*)d_in[4];
    const float* Ws1   = (const float*)d_in[5];
    const float* bs1   = (const float*)d_in[6];
    const float* Ws2   = (const float*)d_in[7];
    const float* bs2   = (const float*)d_in[8];
    const float* raw_h = (const float*)d_in[9];
    const float* fgn   = (const float*)d_in[10];
    float* out = (float*)d_out;

    const int N = in_sizes[10] / in_sizes[0];   // 1000

    k_zero<<<1, 1>>>();
    k_fsde<<<GRID, NTHR>>>(x0, Wd1, bd1, Wd2, bd2, Ws1, bs1, Ws2, bs2,
                           raw_h, fgn, out, N);
}

// round 14
// speedup vs baseline: 1.0029x; 1.0029x over previous
#include <cuda_runtime.h>
#include <math.h>
#include <stdint.h>

#define GRID 128
#define NTHR 512
#define Bv   128
#define Sv   256
#define HDv  512
#define APAD 134          // L1 As row pad
#define A2PADK 17         // L2 As k-major row: 16 rows + 1 pad
#define A2MAT  2192       // L2 As per-mat stride (2176+16 -> bank shift 16)
#define SM_FLOATS 8480    // max(L1: 32*134+128*32=8384, L2: 2*2192+2*2048=8480)

// Persistent device scratch (allocation-free).
__device__ float    g_X[Bv * Sv];        // current SDE state
__device__ float    g_H[2 * Bv * HDv];   // tanh hidden: [0]=drift, [1]=sigma
__device__ unsigned g_bar;               // grid barrier counter (monotone)

__global__ void k_zero() { g_bar = 0u; }

// Grid barrier: release-add + acquire-poll (128 CTAs, all co-resident).
__device__ __forceinline__ void grid_bar(unsigned goal) {
    __syncthreads();
    if (threadIdx.x == 0) {
        unsigned long long ga;
        asm volatile("cvta.to.global.u64 %0, %1;" : "=l"(ga) : "l"(&g_bar));
        asm volatile("red.release.gpu.global.add.u32 [%0], 1;" :: "l"(ga) : "memory");
        unsigned v;
        do {
            asm volatile("ld.acquire.gpu.global.u32 %0, [%1];" : "=r"(v) : "l"(ga) : "memory");
        } while (v < goal);
    }
    __syncthreads();
}

// ---------------------------------------------------------------------------
// L1: 32x32 tile of H = tanh(X @ W1 + b1). K=256 in 2 pipelined passes of 128.
// 8 K-groups x 64 thr, 4x4 micro-tile, smem reduction. (R10 layout + prefetch)
// ---------------------------------------------------------------------------
__device__ __forceinline__ void gemm_l1(
    const float* __restrict__ A,            // g_X [128][256]
    const float* __restrict__ W,            // W1  [256][512]
    const float* __restrict__ bias,
    float* __restrict__ Out,                // H   [128][512]
    int m0, int n0, float* sm)
{
    float* As = sm;               // [32][APAD]
    float* Bs = sm + 32 * APAD;   // [128][32]
    const int t  = threadIdx.x;
    const int g  = t >> 6;
    const int tt = t & 63;
    const int tm = tt >> 3;
    const int tn = tt & 7;

    float acc[4][4];
#pragma unroll
    for (int i = 0; i < 4; i++)
#pragma unroll
        for (int j = 0; j < 4; j++) acc[i][j] = 0.0f;

    float4 pa[2], pb[2];
#pragma unroll
    for (int it = 0; it < 2; it++) {          // prefetch pass 0
        int idx = it * 512 + t;
        int row = idx >> 5, c4 = (idx & 31) << 2;
        pa[it] = __ldcg((const float4*)(A + (m0 + row) * Sv + c4));
        int kr = idx >> 3, c4b = (idx & 7) << 2;
        pb[it] = __ldg((const float4*)(W + kr * HDv + n0 + c4b));
    }

#pragma unroll
    for (int p = 0; p < 2; p++) {
#pragma unroll
        for (int it = 0; it < 2; it++) {      // stage regs -> smem
            int idx = it * 512 + t;
            int row = idx >> 5, c4 = (idx & 31) << 2;
            *((float2*)(As + row * APAD + c4))     = make_float2(pa[it].x, pa[it].y);
            *((float2*)(As + row * APAD + c4 + 2)) = make_float2(pa[it].z, pa[it].w);
            int kr = idx >> 3, c4b = (idx & 7) << 2;
            *((float4*)(Bs + kr * 32 + c4b)) = pb[it];
        }
        __syncthreads();
        if (p == 0) {                         // prefetch pass 1
#pragma unroll
            for (int it = 0; it < 2; it++) {
                int idx = it * 512 + t;
                int row = idx >> 5, c4 = (idx & 31) << 2;
                pa[it] = __ldcg((const float4*)(A + (m0 + row) * Sv + 128 + c4));
                int kr = idx >> 3, c4b = (idx & 7) << 2;
                pb[it] = __ldg((const float4*)(W + (128 + kr) * HDv + n0 + c4b));
            }
        }
        const int k0 = g * 16;
#pragma unroll
        for (int kk = 0; kk < 16; kk++) {
            const int k = k0 + kk;
            float a0 = As[(tm * 4 + 0) * APAD + k];
            float a1 = As[(tm * 4 + 1) * APAD + k];
            float a2 = As[(tm * 4 + 2) * APAD + k];
            float a3 = As[(tm * 4 + 3) * APAD + k];
            float4 b = *((const float4*)(Bs + k * 32 + tn * 4));
            acc[0][0] = fmaf(a0, b.x, acc[0][0]); acc[0][1] = fmaf(a0, b.y, acc[0][1]);
            acc[0][2] = fmaf(a0, b.z, acc[0][2]); acc[0][3] = fmaf(a0, b.w, acc[0][3]);
            acc[1][0] = fmaf(a1, b.x, acc[1][0]); acc[1][1] = fmaf(a1, b.y, acc[1][1]);
            acc[1][2] = fmaf(a1, b.z, acc[1][2]); acc[1][3] = fmaf(a1, b.w, acc[1][3]);
            acc[2][0] = fmaf(a2, b.x, acc[2][0]); acc[2][1] = fmaf(a2, b.y, acc[2][1]);
            acc[2][2] = fmaf(a2, b.z, acc[2][2]); acc[2][3] = fmaf(a2, b.w, acc[2][3]);
            acc[3][0] = fmaf(a3, b.x, acc[3][0]); acc[3][1] = fmaf(a3, b.y, acc[3][1]);
            acc[3][2] = fmaf(a3, b.z, acc[3][2]); acc[3][3] = fmaf(a3, b.w, acc[3][3]);
        }
        __syncthreads();
    }

    // Reduce 8 K-groups via smem, tanh+bias, store H.
    float* R = sm;
#pragma unroll
    for (int i = 0; i < 4; i++) {
        *((float4*)(R + g * 1024 + (tm * 4 + i) * 32 + tn * 4)) =
            make_float4(acc[i][0], acc[i][1], acc[i][2], acc[i][3]);
    }
    __syncthreads();
#pragma unroll
    for (int h = 0; h < 2; h++) {
        int e = h * 512 + t;
        float s = R[e];
#pragma unroll
        for (int gg = 1; gg < 8; gg++) s += R[gg * 1024 + e];
        int m = e >> 5, n = e & 31;
        s = tanhf(s + __ldg(bias + n0 + n));
        __stcg(Out + (m0 + m) * HDv + n0 + n, s);
    }
}

// ---------------------------------------------------------------------------
// L2 + update: 16x16 state tile. Both mats (drift, sigma) computed in this CTA
// over full K=512 (4 pipelined passes of 128), then x updated in-epilogue.
// Threads: mat = t>>8; per mat 8 warps = 8 K-groups; warp micro-tile 2x4
// covers the full 16x16 tile for its k-slice. Smem reduction over warps.
// ---------------------------------------------------------------------------
__device__ __forceinline__ void l2_update(
    const float* __restrict__ Wd2, const float* __restrict__ bd2,
    const float* __restrict__ Ws2, const float* __restrict__ bs2,
    const float* __restrict__ fgn_t,
    float* __restrict__ out, int N, int step,
    float dt, float nscale,
    int m0, int n0, float* sm)
{
    float* As = sm;                    // [2][128][A2PADK] k-major, per-mat stride A2MAT
    float* Bs = sm + 2 * A2MAT;        // [2][128][16]
    const int t    = threadIdx.x;
    const int mat  = t >> 8;
    const int tt   = t & 255;
    const int w    = tt >> 5;          // warp-in-mat 0..7
    const int lane = tt & 31;
    const int tm   = lane >> 2;        // 0..7 -> rows tm*2+{0,1}
    const int tn   = lane & 3;         // 0..3 -> cols tn*4+{0..3}

    // per-thread staging constants
    const int matA = (t & 31) >> 4;                       // A-stage mat
    const int rA   = t & 15;                              // A-stage row
    const float* Astage = g_H + matA * (Bv * HDv) + (m0 + rA) * HDv;
    const int krB  = t >> 2;                              // B-stage k row 0..127
    const int c4b  = (t & 3) << 2;

    // prefetch update operands (hidden behind 4 GEMM passes)
    float xold = 0.0f, fg = 0.0f;
    if (t < 256) {
        int gi_e = (m0 + (t >> 4)) * Sv + n0 + (t & 15);
        xold = __ldcg(&g_X[gi_e]);
        fg   = __ldcs(fgn_t + gi_e);
    }

    float acc[2][4];
#pragma unroll
    for (int i = 0; i < 2; i++)
#pragma unroll
        for (int j = 0; j < 4; j++) acc[i][j] = 0.0f;

    float4 pa[2], pb[2];
#pragma unroll
    for (int it = 0; it < 2; it++) {          // prefetch pass 0 (kp = 0)
        int c4 = (((it * 512 + t) >> 5) << 2);
        pa[it] = __ldcg((const float4*)(Astage + c4));
        const float* Wst = it ? Ws2 : Wd2;
        pb[it] = __ldg((const float4*)(Wst + krB * Sv + n0 + c4b));
    }

#pragma unroll
    for (int p = 0; p < 4; p++) {
#pragma unroll
        for (int it = 0; it < 2; it++) {      // stage regs -> smem
            int c4 = (((it * 512 + t) >> 5) << 2);
            float* a = As + matA * A2MAT + c4 * A2PADK + rA;
            a[0 * A2PADK] = pa[it].x;
            a[1 * A2PADK] = pa[it].y;
            a[2 * A2PADK] = pa[it].z;
            a[3 * A2PADK] = pa[it].w;
            *((float4*)(Bs + it * 2048 + krB * 16 + c4b)) = pb[it];
        }
        __syncthreads();
        if (p < 3) {                          // prefetch pass p+1
            const int kp = (p + 1) * 128;
#pragma unroll
            for (int it = 0; it < 2; it++) {
                int c4 = (((it * 512 + t) >> 5) << 2);
                pa[it] = __ldcg((const float4*)(Astage + kp + c4));
                const float* Wst = it ? Ws2 : Wd2;
                pb[it] = __ldg((const float4*)(Wst + (kp + krB) * Sv + n0 + c4b));
            }
        }
        const float* Asm = As + mat * A2MAT;
        const float* Bsm = Bs + mat * 2048;
#pragma unroll
        for (int kk = 0; kk < 16; kk++) {
            const int kl = w * 16 + kk;
            float a0 = Asm[kl * A2PADK + tm * 2];
            float a1 = Asm[kl * A2PADK + tm * 2 + 1];
            float4 b = *((const float4*)(Bsm + kl * 16 + tn * 4));
            acc[0][0] = fmaf(a0, b.x, acc[0][0]); acc[0][1] = fmaf(a0, b.y, acc[0][1]);
            acc[0][2] = fmaf(a0, b.z, acc[0][2]); acc[0][3] = fmaf(a0, b.w, acc[0][3]);
            acc[1][0] = fmaf(a1, b.x, acc[1][0]); acc[1][1] = fmaf(a1, b.y, acc[1][1]);
            acc[1][2] = fmaf(a1, b.z, acc[1][2]); acc[1][3] = fmaf(a1, b.w, acc[1][3]);
        }
        __syncthreads();
    }

    // Reduce 8 warps per mat via smem (overlays As region), then update x.
    float* R = sm;                            // [2][8][256]
#pragma unroll
    for (int i = 0; i < 2; i++) {
        *((float4*)(R + mat * 2048 + w * 256 + (tm * 2 + i) * 16 + tn * 4)) =
            make_float4(acc[i][0], acc[i][1], acc[i][2], acc[i][3]);
    }
    __syncthreads();
    if (t < 256) {
        float dsum = R[t], ssum = R[2048 + t];
#pragma unroll
        for (int gg = 1; gg < 8; gg++) {
            dsum += R[gg * 256 + t];
            ssum += R[2048 + gg * 256 + t];
        }
        const int col = t & 15;
        const int row = t >> 4;
        dsum += __ldg(bd2 + n0 + col);
        ssum += __ldg(bs2 + n0 + col);
        float x = xold + dsum * dt + ssum * (nscale * fg);
        const int gi_e = (m0 + row) * Sv + n0 + col;
        __stcg(&g_X[gi_e], x);
        __stcs(out + (size_t)(m0 + row) * (size_t)(N + 1) * Sv
                   + (size_t)(step + 1) * Sv + n0 + col, x);
    }
}

// ---------------------------------------------------------------------------
// One persistent kernel: init, then N x { L1 | bar | L2+update | bar }.
// ---------------------------------------------------------------------------
__global__ __launch_bounds__(NTHR) void k_fsde(
    const float* __restrict__ x0,
    const float* __restrict__ Wd1, const float* __restrict__ bd1,
    const float* __restrict__ Wd2, const float* __restrict__ bd2,
    const float* __restrict__ Ws1, const float* __restrict__ bs1,
    const float* __restrict__ Ws2, const float* __restrict__ bs2,
    const float* __restrict__ raw_h,
    const float* __restrict__ fgn,
    float* __restrict__ out, int N)
{
    __shared__ float sm[SM_FLOATS];

    const int bx = blockIdx.x;
    const int t  = threadIdx.x;

    // init: g_X and trajectory slice 0
    if (t < 256) {
        int gi = bx * 256 + t;
        float v = __ldg(x0 + gi);
        __stcg(&g_X[gi], v);
        out[(size_t)(gi >> 8) * (size_t)(N + 1) * Sv + (gi & (Sv - 1))] = v;
    }

    const float dt = 1.0f / (float)N;
    const float rh = __ldg(raw_h);
    const float Hh = 0.98f / (1.0f + expf(-rh)) + 0.01f;
    const float nscale = (float)exp((double)Hh * log(1.0 / (double)N)); // dt^H

    // L1 decode: 2 mats x 4 mtiles x 16 ntiles = 128 CTAs
    const int mat1 = bx >> 6;
    const int m01  = ((bx >> 4) & 3) * 32;
    const int n01  = (bx & 15) * 32;
    const float* W1 = mat1 ? Ws1 : Wd1;
    const float* b1 = mat1 ? bs1 : bd1;
    float* H1 = g_H + mat1 * (Bv * HDv);

    // L2 decode: 8 mtiles x 16 ntiles = 128 CTAs (16x16 state tiles)
    const int m02 = (bx >> 4) * 16;
    const int n02 = (bx & 15) * 16;

    unsigned goal = GRID;
    grid_bar(goal); goal += GRID;          // X published

    for (int step = 0; step < N; step++) {
        gemm_l1(g_X, W1, b1, H1, m01, n01, sm);
        grid_bar(goal); goal += GRID;      // H ready

        l2_update(Wd2, bd2, Ws2, bs2, fgn + (size_t)step * (Bv * Sv),
                  out, N, step, dt, nscale, m02, n02, sm);
        grid_bar(goal); goal += GRID;      // X ready for next step
    }
}

// ---------------------------------------------------------------------------
// Host launcher: 2 graph nodes, fully capturable, allocation-free.
// ---------------------------------------------------------------------------
extern "C" void kernel_launch(void* const* d_in, const int* in_sizes, int n_in,
                              void* d_out, int out_size) {
    const float* x0    = (const float*)d_in[0];
    const float* Wd1   = (const float*)d_in[1];
    const float* bd1   = (const float*)d_in[2];
    const float* Wd2   = (const float*)d_in[3];
    const float* bd2   = (const float*)d_in[4];
    const float* Ws1   = (const float*)d_in[5];
    const float* bs1   = (const float*)d_in[6];
    const float* Ws2   = (const float*)d_in[7];
    const float* bs2   = (const float*)d_in[8];
    const float* raw_h = (const float*)d_in[9];
    const float* fgn   = (const float*)d_in[10];
    float* out = (float*)d_out;

    const int N = in_sizes[10] / in_sizes[0];   // 1000

    k_zero<<<1, 1>>>();
    k_fsde<<<GRID, NTHR>>>(x0, Wd1, bd1, Wd2, bd2, Ws1, bs1, Ws2, bs2,
                           raw_h, fgn, out, N);
}